// round 15
// baseline (speedup 1.0000x reference)
#include <cuda_runtime.h>
#include <cuda_fp16.h>
#include <cstdint>

#define EPS 1e-5f

// ---------------- scratch (no allocations allowed) ----------------
static __device__ float g_featC[2 * 128 * 400];             // [b][c][i]  (t-flat for const path)
static __device__ float g_featI[2 * 400 * 128];             // [b][i][c]  (for att)
static __device__ float g_scores[2 * 400 * 400];            // [b][s][p]
static __device__ float g_W2sum[9 * 128 * 128];             // [cls][o_in][o_out]
static __device__ float g_w2T[128 * 128];                   // [c][co]
static __device__ float g_AL[200 * 128];                    // [s-200][o], pre-scaled by a1
static __device__ float g_BE[200 * 128];                    // pre-scaled by a1
static __device__ float g_C1[128];
static __device__ float g_A2[128];
static __device__ float g_C2[128];
static __device__ float g_W3[128];
static __device__ float g_bn3[2];                           // a3, c3
// f16 A fragments [tap][mhalf(2)][kk][mquarter(4)][lane][4xb32]; padded
static __device__ __align__(16) uint32_t g_wAf[20480 * 4];

__device__ __forceinline__ float silu_f(float y) {
    return y * (1.0f / (1.0f + __expf(-y)));
}
__device__ __forceinline__ void mma_f16(float* d, uint32_t a0, uint32_t a1, uint32_t a2, uint32_t a3,
                                        uint32_t b0, uint32_t b1) {
    asm volatile(
        "mma.sync.aligned.m16n8k16.row.col.f32.f16.f16.f32 "
        "{%0,%1,%2,%3}, {%4,%5,%6,%7}, {%8,%9}, {%0,%1,%2,%3};\n"
        : "+f"(d[0]), "+f"(d[1]), "+f"(d[2]), "+f"(d[3])
        : "r"(a0), "r"(a1), "r"(a2), "r"(a3), "r"(b0), "r"(b1));
}
__device__ __forceinline__ void ldsm_x4(uint32_t& r0, uint32_t& r1, uint32_t& r2, uint32_t& r3,
                                        uint32_t saddr) {
    asm volatile("ldmatrix.sync.aligned.m8n8.x4.shared.b16 {%0,%1,%2,%3}, [%4];"
                 : "=r"(r0), "=r"(r1), "=r"(r2), "=r"(r3) : "r"(saddr));
}

// ---------------- prep A: fragments + W2sum/w2T (blocks 0..135) ----------------
__global__ __launch_bounds__(256)
void prep_w_kernel(const float* __restrict__ wr2, const float* __restrict__ w2) {
    int blk = blockIdx.x;
    int tid = threadIdx.x;
    if (blk < 72) {
        int t = blk * 256 + tid;
        if (t < 18432) {
            int lane = t & 31;
            int mt   = (t >> 5) & 3;
            int kk   = (t >> 7) & 7;
            int wm   = (t >> 10) & 1;
            int tap  = t >> 11;
            int m0 = wm * 64 + mt * 16 + (lane >> 2);
            int k0 = kk * 16 + 2 * (lane & 3);
            float f[8];
            f[0] = wr2[(m0 * 128 + k0) * 9 + tap];
            f[1] = wr2[(m0 * 128 + k0 + 1) * 9 + tap];
            f[2] = wr2[((m0 + 8) * 128 + k0) * 9 + tap];
            f[3] = wr2[((m0 + 8) * 128 + k0 + 1) * 9 + tap];
            f[4] = wr2[(m0 * 128 + k0 + 8) * 9 + tap];
            f[5] = wr2[(m0 * 128 + k0 + 9) * 9 + tap];
            f[6] = wr2[((m0 + 8) * 128 + k0 + 8) * 9 + tap];
            f[7] = wr2[((m0 + 8) * 128 + k0 + 9) * 9 + tap];
            uint32_t u[4];
#pragma unroll
            for (int i = 0; i < 4; i++) {
                uint32_t lo = __half_as_ushort(__float2half_rn(f[2 * i]));
                uint32_t hi = __half_as_ushort(__float2half_rn(f[2 * i + 1]));
                u[i] = lo | (hi << 16);
            }
            ((uint4*)g_wAf)[t] = make_uint4(u[0], u[1], u[2], u[3]);
        }
    } else {
        int t = (blk - 72) * 256 + tid;
        if (t < 16384) {
            int op = t >> 7;
            int o  = t & 127;
            float w[9];
#pragma unroll
            for (int tap = 0; tap < 9; tap++) w[tap] = wr2[(op * 128 + o) * 9 + tap];
#pragma unroll
            for (int hc = 0; hc < 3; hc++) {
#pragma unroll
                for (int wc = 0; wc < 3; wc++) {
                    float s = 0.f;
#pragma unroll
                    for (int dh = 0; dh < 3; dh++) {
                        if (hc == 0 && dh == 0) continue;
                        if (hc == 2 && dh == 2) continue;
#pragma unroll
                        for (int dw = 0; dw < 3; dw++) {
                            if (wc == 0 && dw == 0) continue;
                            if (wc == 2 && dw == 2) continue;
                            s += w[dh * 3 + dw];
                        }
                    }
                    g_W2sum[((hc * 3 + wc) * 128 + o) * 128 + op] = s;
                }
            }
            g_w2T[o * 128 + op] = w2[op * 128 + o];
        }
    }
}

// ---------------- prep B: per-sample alpha/beta (xa1) + bn constants ----------------
__global__ __launch_bounds__(256)
void prep_ab_kernel(const float* __restrict__ wr1,
                    const float* __restrict__ gr1, const float* __restrict__ br1,
                    const float* __restrict__ mr1, const float* __restrict__ vr1,
                    const float* __restrict__ gr2, const float* __restrict__ br2,
                    const float* __restrict__ mr2, const float* __restrict__ vr2,
                    const float* __restrict__ wr3,
                    const float* __restrict__ gr3, const float* __restrict__ br3,
                    const float* __restrict__ mr3, const float* __restrict__ vr3) {
    __shared__ float warpsum[8];
    __shared__ float Pex[258];
    int o = blockIdx.x;          // 0..127
    int t = threadIdx.x;         // 256
    int lane = t & 31, w = t >> 5;
    float v = wr1[o * 256 + t];
    float x = v;
#pragma unroll
    for (int d = 1; d < 32; d <<= 1) {
        float y = __shfl_up_sync(0xffffffffu, x, d);
        if (lane >= d) x += y;
    }
    if (lane == 31) warpsum[w] = x;
    __syncthreads();
    if (t == 0) {
        float r = 0.f;
#pragma unroll
        for (int i = 0; i < 8; i++) { float tmp = warpsum[i]; warpsum[i] = r; r += tmp; }
        Pex[256] = r;
    }
    __syncthreads();
    float incl = x + warpsum[w];
    Pex[t] = incl - v;
    __syncthreads();
    float a1 = gr1[o] * rsqrtf(vr1[o] + EPS);
    if (t == 0) {
        g_C1[o] = br1[o] - mr1[o] * a1;
        float a2 = gr2[o] * rsqrtf(vr2[o] + EPS);
        g_A2[o] = a2;
        g_C2[o] = br2[o] - mr2[o] * a2;
        g_W3[o] = wr3[o];
        if (o == 0) {
            float a3 = gr3[0] * rsqrtf(vr3[0] + EPS);
            g_bn3[0] = a3;
            g_bn3[1] = br3[0] - mr3[0] * a3;
        }
    }
    if (t < 200) {
        int s = 200 + t;
        int r0 = (s * 256) % 400;
        int usplit = 400 - r0;
        if (usplit > 256) usplit = 256;
        float total = Pex[256];
        float al = (usplit == 256) ? total : Pex[usplit];
        g_AL[t * 128 + o] = a1 * al;
        g_BE[t * 128 + o] = a1 * (total - al);
    }
}

// ---------------- feat = CBS(x, w1): c-major + i-major copies ----------------
__global__ __launch_bounds__(256)
void feat_kernel(const float* __restrict__ x, const float* __restrict__ w1,
                 const float* __restrict__ g1, const float* __restrict__ b1,
                 const float* __restrict__ m1, const float* __restrict__ v1) {
    __shared__ float wrow[128];
    __shared__ float psum[128];
    int bc = blockIdx.x;             // 256 = 2b * 128c
    int b = bc >> 7, c = bc & 127;
    int tid = threadIdx.x;           // 256
    int p = tid & 127;
    int t2 = tid >> 7;               // cin half
    if (tid < 128) wrow[tid] = w1[c * 128 + tid];
    __syncthreads();
    float a  = g1[c] * rsqrtf(v1[c] + EPS);
    float cc = b1[c] - m1[c] * a;
    const float* xb = x + (b * 128 + t2 * 64) * 400;
    const float* wq = wrow + t2 * 64;
    for (int i0 = 0; i0 < 400; i0 += 128) {
        int i = i0 + p;
        float s = 0.f;
        if (i < 400) {
#pragma unroll 16
            for (int cin = 0; cin < 64; cin++)
                s += wq[cin] * xb[cin * 400 + i];
        }
        __syncthreads();
        if (t2) psum[p] = s;
        __syncthreads();
        if (!t2 && i < 400) {
            float fv = silu_f(a * (s + psum[p]) + cc);
            g_featC[(b * 128 + c) * 400 + i] = fv;
            g_featI[b * 51200 + i * 128 + c] = fv;
        }
    }
}

// ---------------- big kernel: spatial (blocks 0..1599) + const (1600..1799) ----------------
#define SQ_Y      0               // 180 rows x 136 halves = 48960 B  (row stride 272 B)
#define SQ_C1     48960           // 128 f
#define SQ_AL     49472           // 128 f
#define SQ_BE     49984           // 128 f
#define SQ_FW     50496           // 320 f
#define SQ_PART   51776           // 512 f (2 wm x 128 cols used)
#define SQ_TOT    53824

__global__ __launch_bounds__(256, 2)
void big_kernel(const float* __restrict__ wr1,
                const float* __restrict__ gr1, const float* __restrict__ br1,
                const float* __restrict__ mr1, const float* __restrict__ vr1) {
    extern __shared__ __align__(16) char smem[];
    int blk = blockIdx.x;
    int tid = threadIdx.x;                // 256
    int wid = tid >> 5;
    int lane = tid & 31;
    int lg = lane >> 2;

    if (blk >= 1600) {
        // ================= const path: 2 samples per CTA =================
        float* smf  = (float*)smem;
        float* fwin = smf;                // 2 x 260
        float* V    = smf + 520;          // 2 x 132
        float* zbuf = smf + 784;          // 2 x 18 x 132
        float* red  = smf + 5536;         // 4 x 18
        float* scb  = smf + 5608;         // 18

        int cblk = blk - 1600;            // 0..199
        int u0 = cblk * 2;
        int o = tid & 127;
        int g = tid >> 7;

        for (int idx = tid; idx < 512; idx += 256) {
            int su = idx >> 8, j = idx & 255;
            fwin[su * 260 + j] = g_featC[(u0 + su) * 256 + j];
        }
        __syncthreads();

        for (int oi = 0; oi < 16; oi++) {
            int oo = wid * 16 + oi;
            float s0 = 0.f, s1 = 0.f;
#pragma unroll
            for (int i = 0; i < 8; i++) {
                float wv = wr1[oo * 256 + i * 32 + lane];
                s0 += wv * fwin[i * 32 + lane];
                s1 += wv * fwin[260 + i * 32 + lane];
            }
#pragma unroll
            for (int m = 16; m > 0; m >>= 1) {
                s0 += __shfl_xor_sync(0xffffffffu, s0, m);
                s1 += __shfl_xor_sync(0xffffffffu, s1, m);
            }
            if (lane == 0) {
                float a1 = gr1[oo] * rsqrtf(vr1[oo] + EPS);
                float c1 = br1[oo] - mr1[oo] * a1;
                V[oo] = silu_f(a1 * s0 + c1);
                V[132 + oo] = silu_f(a1 * s1 + c1);
            }
        }
        __syncthreads();

        float z[18];
#pragma unroll
        for (int i = 0; i < 18; i++) z[i] = 0.f;
        int oo0 = g * 64;
#pragma unroll 1
        for (int oo = oo0; oo < oo0 + 64; oo++) {
            float v0 = V[oo], v1 = V[132 + oo];
#pragma unroll
            for (int cls = 0; cls < 9; cls++) {
                float wv = g_W2sum[(cls * 128 + oo) * 128 + o];
                z[cls * 2]     += wv * v0;
                z[cls * 2 + 1] += wv * v1;
            }
        }
#pragma unroll
        for (int i = 0; i < 18; i++) zbuf[(g * 18 + i) * 132 + o] = z[i];
        __syncthreads();

        if (tid < 128) {
            float a2 = g_A2[o], c2 = g_C2[o], w3 = g_W3[o];
            int wrp = tid >> 5;
#pragma unroll
            for (int i = 0; i < 18; i++) {
                float zf = zbuf[i * 132 + o] + zbuf[(18 + i) * 132 + o];
                float p = w3 * silu_f(a2 * zf + c2);
                p += __shfl_xor_sync(0xffffffffu, p, 1);
                p += __shfl_xor_sync(0xffffffffu, p, 2);
                p += __shfl_xor_sync(0xffffffffu, p, 4);
                p += __shfl_xor_sync(0xffffffffu, p, 8);
                p += __shfl_xor_sync(0xffffffffu, p, 16);
                if (lane == 0) red[wrp * 18 + i] = p;
            }
        }
        __syncthreads();
        if (tid < 18) {
            float tot = red[tid] + red[18 + tid] + red[36 + tid] + red[54 + tid];
            scb[tid] = silu_f(g_bn3[0] * tot + g_bn3[1]);
        }
        __syncthreads();

        for (int idx = tid; idx < 800; idx += 256) {
            int su = idx / 400, p = idx % 400;
            int h = p / 20, w = p % 20;
            int hc = (h == 0) ? 0 : ((h == 19) ? 2 : 1);
            int wc = (w == 0) ? 0 : ((w == 19) ? 2 : 1);
            int u = u0 + su;
            int b = u / 200, s = u % 200;
            g_scores[(b * 400 + s) * 400 + p] = scb[(hc * 3 + wc) * 2 + su];
        }
        return;
    }

    // ================= spatial path =================
    __half* Yh  = (__half*)(smem + SQ_Y);
    float* C1s  = (float*)(smem + SQ_C1);
    float* ALs  = (float*)(smem + SQ_AL);
    float* BEs  = (float*)(smem + SQ_BE);
    float* FAw  = (float*)(smem + SQ_FW);
    float* FBw  = FAw + 160;
    float* PART = (float*)(smem + SQ_PART);

    int b = blk / 800;
    int rem = blk - b * 800;
    int sIdx = rem >> 2;                  // 0..199
    int s = 200 + sIdx;
    int q = rem & 3;                      // quarter: output rows q*5 .. q*5+4

    {
        uint4 z4 = make_uint4(0, 0, 0, 0);
        uint4* Yz = (uint4*)(smem + SQ_Y);
        for (int i = tid; i < 3060; i += 256) Yz[i] = z4;
    }

    int t0 = s * 256;
    int r0 = t0 % 400;
    int usplit = 400 - r0;
    if (usplit > 256) usplit = 256;
    int chA = t0 / 400 - 128;
    int chB = (usplit >= 256) ? chA : (chA + 1);

    if (tid < 128) {
        int o = tid;
        C1s[o] = g_C1[o];
        ALs[o] = g_AL[sIdx * 128 + o];
        BEs[o] = g_BE[sIdx * 128 + o];
    }
    for (int idx = tid; idx < 280; idx += 256) {
        int arr = idx / 140, pos = idx % 140;
        int rw = pos / 20, gw = pos % 20;
        int gh = q * 5 - 1 + rw;
        float v = 0.f;
        if (gh >= 0 && gh < 20)
            v = g_featC[b * 51200 + (arr ? chB : chA) * 400 + gh * 20 + gw];
        (arr ? FBw : FAw)[pos] = v;
    }
    __syncthreads();

    for (int idx = tid; idx < 280; idx += 256) {
        int chh = idx / 140, pos = idx % 140;
        int rw = pos / 20, gw = pos % 20;
        int gh = q * 5 - 1 + rw;
        if (gh >= 0 && gh < 20) {
            float fa = FAw[pos], fb = FBw[pos];
            int rowoff = (rw * 24 + gw + 1) * 136;
#pragma unroll 8
            for (int o2 = 0; o2 < 32; o2++) {
                int o = chh * 64 + o2 * 2;
                float y0 = silu_f(ALs[o] * fa + BEs[o] * fb + C1s[o]);
                float y1 = silu_f(ALs[o + 1] * fa + BEs[o + 1] * fb + C1s[o + 1]);
                *(__half2*)(Yh + rowoff + o) = __floats2half2_rn(y0, y1);
            }
        }
    }
    __syncthreads();

    // warps: wm in {0,1} (M64 half) x wn in {0..3} (N32 quarter)
    // -> B fragments shared by only 2 warps (was 4); LDSM traffic halves.
    int wm = wid >> 2;
    int wn = wid & 3;
    int nb = wn * 32;

    uint32_t Ybase = (uint32_t)__cvta_generic_to_shared(Yh);
    int laneN = lane & 7;
    int sel   = (lane >> 3) & 1;
    int pairN = lane >> 4;
    uint32_t laneTerm = Ybase + (uint32_t)((pairN * 8 + laneN) * 272 + sel * 16);

    float acc[4][4][4];
#pragma unroll
    for (int mt = 0; mt < 4; mt++)
#pragma unroll
        for (int nt = 0; nt < 4; nt++)
#pragma unroll
            for (int c = 0; c < 4; c++) acc[mt][nt][c] = 0.f;

    // A fragments: mtile = wm*4 + mt, stored at (mtile>>2)*1024 + (mtile&3)*32
    const uint4* Aw = ((const uint4*)g_wAf) + wm * 1024 + lane;

    uint32_t bv0[2][4], bv1[2][4];
    uint32_t rowa = laneTerm + (uint32_t)(nb * 272);
    ldsm_x4(bv0[0][0], bv1[0][0], bv0[0][1], bv1[0][1], rowa);
    ldsm_x4(bv0[0][2], bv1[0][2], bv0[0][3], bv1[0][3], rowa + 4352);

#pragma unroll 1
    for (int tap = 0; tap < 9; tap++) {
        int tap1 = (tap < 8) ? tap + 1 : 8;
        int dh1 = tap1 / 3, dw1 = tap1 - dh1 * 3;
        uint32_t rowan = laneTerm + (uint32_t)((nb + dh1 * 24 + dw1) * 272);
        const uint4* At = Aw + tap * 2048;
#pragma unroll
        for (int kk = 0; kk < 8; kk++) {
            int pp = kk & 1;
            int np = pp ^ 1;
            // prefetch B for next (kk, tap)
            uint32_t na = (kk < 7) ? (rowa + (uint32_t)((kk + 1) * 32)) : rowan;
            ldsm_x4(bv0[np][0], bv1[np][0], bv0[np][1], bv1[np][1], na);
            ldsm_x4(bv0[np][2], bv1[np][2], bv0[np][3], bv1[np][3], na + 4352);
            // A fragments for this (tap, kk): 4 m16 tiles (L1-resident)
            const uint4* Ai = At + kk * 128;
            uint4 av0 = __ldg(Ai);
            uint4 av1 = __ldg(Ai + 32);
            uint4 av2 = __ldg(Ai + 64);
            uint4 av3 = __ldg(Ai + 96);
#pragma unroll
            for (int nt = 0; nt < 4; nt++) {
                mma_f16(acc[0][nt], av0.x, av0.y, av0.z, av0.w, bv0[pp][nt], bv1[pp][nt]);
                mma_f16(acc[1][nt], av1.x, av1.y, av1.z, av1.w, bv0[pp][nt], bv1[pp][nt]);
                mma_f16(acc[2][nt], av2.x, av2.y, av2.z, av2.w, bv0[pp][nt], bv1[pp][nt]);
                mma_f16(acc[3][nt], av3.x, av3.y, av3.z, av3.w, bv0[pp][nt], bv1[pp][nt]);
            }
        }
        rowa = rowan;
    }

    float a3 = g_bn3[0];
    float c3 = g_bn3[1];

    float pnt[4][2];
#pragma unroll
    for (int nt = 0; nt < 4; nt++) { pnt[nt][0] = 0.f; pnt[nt][1] = 0.f; }

#pragma unroll
    for (int mt = 0; mt < 4; mt++) {
#pragma unroll
        for (int rs = 0; rs < 2; rs++) {
            int m = wm * 64 + mt * 16 + rs * 8 + lg;
            float a2m = g_A2[m], c2m = g_C2[m], w3m = g_W3[m];
#pragma unroll
            for (int nt = 0; nt < 4; nt++) {
#pragma unroll
                for (int cc = 0; cc < 2; cc++) {
                    float zv = silu_f(a2m * acc[mt][nt][rs * 2 + cc] + c2m);
                    pnt[nt][cc] += w3m * zv;
                }
            }
        }
    }
#pragma unroll
    for (int nt = 0; nt < 4; nt++) {
#pragma unroll
        for (int cc = 0; cc < 2; cc++) {
            float v = pnt[nt][cc];
            v += __shfl_xor_sync(0xffffffffu, v, 4);
            v += __shfl_xor_sync(0xffffffffu, v, 8);
            v += __shfl_xor_sync(0xffffffffu, v, 16);
            if (lane < 4)
                PART[wm * 128 + nb + nt * 8 + 2 * lane + cc] = v;
        }
    }
    __syncthreads();

    if (tid < 128) {
        int n = tid;
        int hl = n / 24, wc = n % 24;
        if (hl < 5 && wc < 20) {
            float v = PART[n] + PART[128 + n];
            int h = q * 5 + hl;
            g_scores[(b * 400 + s) * 400 + h * 20 + wc] = silu_f(a3 * v + c3);
        }
    }
}

// ---------------- attention: 4 rows/CTA, coalesced featI, j/k 2-way split ----------------
__global__ __launch_bounds__(256)
void att_kernel(const float* __restrict__ x,
                const float* __restrict__ g2, const float* __restrict__ b2,
                const float* __restrict__ m2, const float* __restrict__ v2,
                float* __restrict__ out) {
    __shared__ float srow[4][400];
    __shared__ float attp[4][132];
    __shared__ float atts[4][132];
    __shared__ float yp[4][132];

    int blk = blockIdx.x;               // 200 = 2b * 50
    int b = blk / 100;
    int i0 = (blk % 100) * 4;
    int tid = threadIdx.x;              // 256
    int c = tid & 127;
    int g = tid >> 7;                   // 0,1

    for (int idx = tid; idx < 1600; idx += 256) {
        int r = idx / 400, j = idx - r * 400;
        srow[r][j] = g_scores[(b * 400 + i0 + r) * 400 + j];
    }
    __syncthreads();

    float acc[4] = {0.f, 0.f, 0.f, 0.f};
    {
        const float* fI = g_featI + b * 51200 + c;
        int j0 = g * 200;
#pragma unroll 4
        for (int j = j0; j < j0 + 200; j++) {
            float fv = fI[j * 128];
#pragma unroll
            for (int r = 0; r < 4; r++) acc[r] += srow[r][j] * fv;
        }
    }
    if (g) {
#pragma unroll
        for (int r = 0; r < 4; r++) attp[r][c] = acc[r];
    }
    __syncthreads();
    if (!g) {
#pragma unroll
        for (int r = 0; r < 4; r++) atts[r][c] = acc[r] + attp[r][c];
    }
    __syncthreads();

    float y[4] = {0.f, 0.f, 0.f, 0.f};
    {
        int k0 = g * 64;
#pragma unroll 8
        for (int k = k0; k < k0 + 64; k++) {
            float wv = g_w2T[k * 128 + c];
#pragma unroll
            for (int r = 0; r < 4; r++) y[r] += wv * atts[r][k];
        }
    }
    if (g) {
#pragma unroll
        for (int r = 0; r < 4; r++) yp[r][c] = y[r];
    }
    __syncthreads();
    if (!g) {
        float a  = g2[c] * rsqrtf(v2[c] + EPS);
        float cn = b2[c] - m2[c] * a;
#pragma unroll
        for (int r = 0; r < 4; r++) {
            int i = i0 + r;
            float yy = y[r] + yp[r][c];
            out[(b * 128 + c) * 400 + i] = silu_f(a * yy + cn) + x[(b * 128 + c) * 400 + i];
        }
    }
}

// ---------------- launcher ----------------
extern "C" void kernel_launch(void* const* d_in, const int* in_sizes, int n_in,
                              void* d_out, int out_size) {
    (void)in_sizes; (void)n_in; (void)out_size;
    const float* x   = (const float*)d_in[0];
    const float* w1  = (const float*)d_in[1];
    const float* g1  = (const float*)d_in[2];
    const float* b1  = (const float*)d_in[3];
    const float* m1  = (const float*)d_in[4];
    const float* v1  = (const float*)d_in[5];
    const float* w2  = (const float*)d_in[6];
    const float* g2  = (const float*)d_in[7];
    const float* b2  = (const float*)d_in[8];
    const float* m2  = (const float*)d_in[9];
    const float* v2  = (const float*)d_in[10];
    const float* wr1 = (const float*)d_in[11];
    const float* gr1 = (const float*)d_in[12];
    const float* br1 = (const float*)d_in[13];
    const float* mr1 = (const float*)d_in[14];
    const float* vr1 = (const float*)d_in[15];
    const float* wr2 = (const float*)d_in[16];
    const float* gr2 = (const float*)d_in[17];
    const float* br2 = (const float*)d_in[18];
    const float* mr2 = (const float*)d_in[19];
    const float* vr2 = (const float*)d_in[20];
    const float* wr3 = (const float*)d_in[21];
    const float* gr3 = (const float*)d_in[22];
    const float* br3 = (const float*)d_in[23];
    const float* mr3 = (const float*)d_in[24];
    const float* vr3 = (const float*)d_in[25];
    float* out = (float*)d_out;

    cudaFuncSetAttribute(big_kernel, cudaFuncAttributeMaxDynamicSharedMemorySize, SQ_TOT);

    // big_kernel at launch #4 -> ncu capture verifies the retile.
    prep_w_kernel<<<136, 256>>>(wr2, w2);
    prep_ab_kernel<<<128, 256>>>(wr1, gr1, br1, mr1, vr1, gr2, br2, mr2, vr2,
                                 wr3, gr3, br3, mr3, vr3);
    feat_kernel<<<256, 256>>>(x, w1, g1, b1, m1, v1);
    big_kernel<<<1800, 256, SQ_TOT>>>(wr1, gr1, br1, mr1, vr1);
    att_kernel<<<200, 256>>>(x, g2, b2, m2, v2, out);
}

// round 16
// speedup vs baseline: 1.0407x; 1.0407x over previous
#include <cuda_runtime.h>
#include <cuda_fp16.h>
#include <cstdint>

#define EPS 1e-5f

// ---------------- scratch (no allocations allowed) ----------------
static __device__ float g_featC[2 * 128 * 400];             // [b][c][i]  (t-flat for const path)
static __device__ float g_featI[2 * 400 * 128];             // [b][i][c]  (for att)
static __device__ float g_scores[2 * 400 * 400];            // [b][s][p]
static __device__ float g_W2sum[9 * 128 * 128];             // [cls][o_in][o_out]
static __device__ float g_w2T[128 * 128];                   // [c][co]
static __device__ float g_AL[200 * 128];                    // [s-200][o], pre-scaled by a1
static __device__ float g_BE[200 * 128];                    // pre-scaled by a1
static __device__ float g_C1[128];
static __device__ float g_A2[128];
static __device__ float g_C2[128];
static __device__ float g_W3[128];
static __device__ float g_bn3[2];                           // a3, c3
// f16 A fragments [tap][wm(2)][kk][mt(4)][lane][4xb32]; padded for tap==9 prefetch
static __device__ __align__(16) uint32_t g_wAf[20480 * 4];

__device__ __forceinline__ float silu_f(float y) {
    return y * (1.0f / (1.0f + __expf(-y)));
}
__device__ __forceinline__ void mma_f16(float* d, uint32_t a0, uint32_t a1, uint32_t a2, uint32_t a3,
                                        uint32_t b0, uint32_t b1) {
    asm volatile(
        "mma.sync.aligned.m16n8k16.row.col.f32.f16.f16.f32 "
        "{%0,%1,%2,%3}, {%4,%5,%6,%7}, {%8,%9}, {%0,%1,%2,%3};\n"
        : "+f"(d[0]), "+f"(d[1]), "+f"(d[2]), "+f"(d[3])
        : "r"(a0), "r"(a1), "r"(a2), "r"(a3), "r"(b0), "r"(b1));
}
__device__ __forceinline__ void ldsm_x4(uint32_t& r0, uint32_t& r1, uint32_t& r2, uint32_t& r3,
                                        uint32_t saddr) {
    asm volatile("ldmatrix.sync.aligned.m8n8.x4.shared.b16 {%0,%1,%2,%3}, [%4];"
                 : "=r"(r0), "=r"(r1), "=r"(r2), "=r"(r3) : "r"(saddr));
}

// ---------------- fused prep: fragments + W2sum/w2T (0..135) + ab (136..263) ----------------
__global__ __launch_bounds__(256)
void prep_all_kernel(const float* __restrict__ wr2, const float* __restrict__ w2,
                     const float* __restrict__ wr1,
                     const float* __restrict__ gr1, const float* __restrict__ br1,
                     const float* __restrict__ mr1, const float* __restrict__ vr1,
                     const float* __restrict__ gr2, const float* __restrict__ br2,
                     const float* __restrict__ mr2, const float* __restrict__ vr2,
                     const float* __restrict__ wr3,
                     const float* __restrict__ gr3, const float* __restrict__ br3,
                     const float* __restrict__ mr3, const float* __restrict__ vr3) {
    __shared__ float warpsum[8];
    __shared__ float Pex[258];
    int blk = blockIdx.x;
    int tid = threadIdx.x;

    if (blk < 72) {
        // ---- f16 A fragments ----
        int t = blk * 256 + tid;
        if (t < 18432) {
            int lane = t & 31;
            int mt   = (t >> 5) & 3;
            int kk   = (t >> 7) & 7;
            int wm   = (t >> 10) & 1;
            int tap  = t >> 11;
            int m0 = wm * 64 + mt * 16 + (lane >> 2);
            int k0 = kk * 16 + 2 * (lane & 3);
            float f[8];
            f[0] = wr2[(m0 * 128 + k0) * 9 + tap];
            f[1] = wr2[(m0 * 128 + k0 + 1) * 9 + tap];
            f[2] = wr2[((m0 + 8) * 128 + k0) * 9 + tap];
            f[3] = wr2[((m0 + 8) * 128 + k0 + 1) * 9 + tap];
            f[4] = wr2[(m0 * 128 + k0 + 8) * 9 + tap];
            f[5] = wr2[(m0 * 128 + k0 + 9) * 9 + tap];
            f[6] = wr2[((m0 + 8) * 128 + k0 + 8) * 9 + tap];
            f[7] = wr2[((m0 + 8) * 128 + k0 + 9) * 9 + tap];
            uint32_t u[4];
#pragma unroll
            for (int i = 0; i < 4; i++) {
                uint32_t lo = __half_as_ushort(__float2half_rn(f[2 * i]));
                uint32_t hi = __half_as_ushort(__float2half_rn(f[2 * i + 1]));
                u[i] = lo | (hi << 16);
            }
            ((uint4*)g_wAf)[t] = make_uint4(u[0], u[1], u[2], u[3]);
        }
    } else if (blk < 136) {
        // ---- W2sum + w2T ----
        int t = (blk - 72) * 256 + tid;
        if (t < 16384) {
            int op = t >> 7;
            int o  = t & 127;
            float w[9];
#pragma unroll
            for (int tap = 0; tap < 9; tap++) w[tap] = wr2[(op * 128 + o) * 9 + tap];
#pragma unroll
            for (int hc = 0; hc < 3; hc++) {
#pragma unroll
                for (int wc = 0; wc < 3; wc++) {
                    float s = 0.f;
#pragma unroll
                    for (int dh = 0; dh < 3; dh++) {
                        if (hc == 0 && dh == 0) continue;
                        if (hc == 2 && dh == 2) continue;
#pragma unroll
                        for (int dw = 0; dw < 3; dw++) {
                            if (wc == 0 && dw == 0) continue;
                            if (wc == 2 && dw == 2) continue;
                            s += w[dh * 3 + dw];
                        }
                    }
                    g_W2sum[((hc * 3 + wc) * 128 + o) * 128 + op] = s;
                }
            }
            g_w2T[o * 128 + op] = w2[op * 128 + o];
        }
    } else {
        // ---- per-sample alpha/beta (xa1) + bn constants; o = blk-136 ----
        int o = blk - 136;
        int t = tid;
        int lane = t & 31, w = t >> 5;
        float v = wr1[o * 256 + t];
        float x = v;
#pragma unroll
        for (int d = 1; d < 32; d <<= 1) {
            float y = __shfl_up_sync(0xffffffffu, x, d);
            if (lane >= d) x += y;
        }
        if (lane == 31) warpsum[w] = x;
        __syncthreads();
        if (t == 0) {
            float r = 0.f;
#pragma unroll
            for (int i = 0; i < 8; i++) { float tmp = warpsum[i]; warpsum[i] = r; r += tmp; }
            Pex[256] = r;
        }
        __syncthreads();
        float incl = x + warpsum[w];
        Pex[t] = incl - v;
        __syncthreads();
        float a1 = gr1[o] * rsqrtf(vr1[o] + EPS);
        if (t == 0) {
            g_C1[o] = br1[o] - mr1[o] * a1;
            float a2 = gr2[o] * rsqrtf(vr2[o] + EPS);
            g_A2[o] = a2;
            g_C2[o] = br2[o] - mr2[o] * a2;
            g_W3[o] = wr3[o];
            if (o == 0) {
                float a3 = gr3[0] * rsqrtf(vr3[0] + EPS);
                g_bn3[0] = a3;
                g_bn3[1] = br3[0] - mr3[0] * a3;
            }
        }
        if (t < 200) {
            int s = 200 + t;
            int r0 = (s * 256) % 400;
            int usplit = 400 - r0;
            if (usplit > 256) usplit = 256;
            float total = Pex[256];
            float al = (usplit == 256) ? total : Pex[usplit];
            g_AL[t * 128 + o] = a1 * al;
            g_BE[t * 128 + o] = a1 * (total - al);
        }
    }
}

// ---------------- feat = CBS(x, w1): c-major + i-major copies ----------------
__global__ __launch_bounds__(256)
void feat_kernel(const float* __restrict__ x, const float* __restrict__ w1,
                 const float* __restrict__ g1, const float* __restrict__ b1,
                 const float* __restrict__ m1, const float* __restrict__ v1) {
    __shared__ float wrow[128];
    __shared__ float psum[128];
    int bc = blockIdx.x;             // 256 = 2b * 128c
    int b = bc >> 7, c = bc & 127;
    int tid = threadIdx.x;           // 256
    int p = tid & 127;
    int t2 = tid >> 7;               // cin half
    if (tid < 128) wrow[tid] = w1[c * 128 + tid];
    __syncthreads();
    float a  = g1[c] * rsqrtf(v1[c] + EPS);
    float cc = b1[c] - m1[c] * a;
    const float* xb = x + (b * 128 + t2 * 64) * 400;
    const float* wq = wrow + t2 * 64;
    for (int i0 = 0; i0 < 400; i0 += 128) {
        int i = i0 + p;
        float s = 0.f;
        if (i < 400) {
#pragma unroll 16
            for (int cin = 0; cin < 64; cin++)
                s += wq[cin] * xb[cin * 400 + i];
        }
        __syncthreads();
        if (t2) psum[p] = s;
        __syncthreads();
        if (!t2 && i < 400) {
            float fv = silu_f(a * (s + psum[p]) + cc);
            g_featC[(b * 128 + c) * 400 + i] = fv;
            g_featI[b * 51200 + i * 128 + c] = fv;
        }
    }
}

// ---------------- big kernel: spatial (blocks 0..1599) + const (1600..1799) ----------------
#define SQ_Y      0               // 180 rows x 136 halves = 48960 B  (row stride 272 B)
#define SQ_C1     48960           // 128 f
#define SQ_AL     49472           // 128 f
#define SQ_BE     49984           // 128 f
#define SQ_FW     50496           // 320 f
#define SQ_PART   51776           // 512 f (4 wm x 128 cols)
#define SQ_TOT    53824

__global__ __launch_bounds__(256, 2)
void big_kernel(const float* __restrict__ wr1,
                const float* __restrict__ gr1, const float* __restrict__ br1,
                const float* __restrict__ mr1, const float* __restrict__ vr1) {
    extern __shared__ __align__(16) char smem[];
    int blk = blockIdx.x;
    int tid = threadIdx.x;                // 256
    int wid = tid >> 5;
    int lane = tid & 31;
    int lg = lane >> 2;

    if (blk >= 1600) {
        // ================= const path: 2 samples per CTA =================
        float* smf  = (float*)smem;
        float* fwin = smf;                // 2 x 260
        float* V    = smf + 520;          // 2 x 132
        float* zbuf = smf + 784;          // 2 x 18 x 132
        float* red  = smf + 5536;         // 4 x 18
        float* scb  = smf + 5608;         // 18

        int cblk = blk - 1600;            // 0..199
        int u0 = cblk * 2;
        int o = tid & 127;
        int g = tid >> 7;

        for (int idx = tid; idx < 512; idx += 256) {
            int su = idx >> 8, j = idx & 255;
            fwin[su * 260 + j] = g_featC[(u0 + su) * 256 + j];
        }
        __syncthreads();

        for (int oi = 0; oi < 16; oi++) {
            int oo = wid * 16 + oi;
            float s0 = 0.f, s1 = 0.f;
#pragma unroll
            for (int i = 0; i < 8; i++) {
                float wv = wr1[oo * 256 + i * 32 + lane];
                s0 += wv * fwin[i * 32 + lane];
                s1 += wv * fwin[260 + i * 32 + lane];
            }
#pragma unroll
            for (int m = 16; m > 0; m >>= 1) {
                s0 += __shfl_xor_sync(0xffffffffu, s0, m);
                s1 += __shfl_xor_sync(0xffffffffu, s1, m);
            }
            if (lane == 0) {
                float a1 = gr1[oo] * rsqrtf(vr1[oo] + EPS);
                float c1 = br1[oo] - mr1[oo] * a1;
                V[oo] = silu_f(a1 * s0 + c1);
                V[132 + oo] = silu_f(a1 * s1 + c1);
            }
        }
        __syncthreads();

        float z[18];
#pragma unroll
        for (int i = 0; i < 18; i++) z[i] = 0.f;
        int oo0 = g * 64;
#pragma unroll 1
        for (int oo = oo0; oo < oo0 + 64; oo++) {
            float v0 = V[oo], v1 = V[132 + oo];
#pragma unroll
            for (int cls = 0; cls < 9; cls++) {
                float wv = g_W2sum[(cls * 128 + oo) * 128 + o];
                z[cls * 2]     += wv * v0;
                z[cls * 2 + 1] += wv * v1;
            }
        }
#pragma unroll
        for (int i = 0; i < 18; i++) zbuf[(g * 18 + i) * 132 + o] = z[i];
        __syncthreads();

        if (tid < 128) {
            float a2 = g_A2[o], c2 = g_C2[o], w3 = g_W3[o];
            int wrp = tid >> 5;
#pragma unroll
            for (int i = 0; i < 18; i++) {
                float zf = zbuf[i * 132 + o] + zbuf[(18 + i) * 132 + o];
                float p = w3 * silu_f(a2 * zf + c2);
                p += __shfl_xor_sync(0xffffffffu, p, 1);
                p += __shfl_xor_sync(0xffffffffu, p, 2);
                p += __shfl_xor_sync(0xffffffffu, p, 4);
                p += __shfl_xor_sync(0xffffffffu, p, 8);
                p += __shfl_xor_sync(0xffffffffu, p, 16);
                if (lane == 0) red[wrp * 18 + i] = p;
            }
        }
        __syncthreads();
        if (tid < 18) {
            float tot = red[tid] + red[18 + tid] + red[36 + tid] + red[54 + tid];
            scb[tid] = silu_f(g_bn3[0] * tot + g_bn3[1]);
        }
        __syncthreads();

        for (int idx = tid; idx < 800; idx += 256) {
            int su = idx / 400, p = idx % 400;
            int h = p / 20, w = p % 20;
            int hc = (h == 0) ? 0 : ((h == 19) ? 2 : 1);
            int wc = (w == 0) ? 0 : ((w == 19) ? 2 : 1);
            int u = u0 + su;
            int b = u / 200, s = u % 200;
            g_scores[(b * 400 + s) * 400 + p] = scb[(hc * 3 + wc) * 2 + su];
        }
        return;
    }

    // ================= spatial path (R14 configuration) =================
    __half* Yh  = (__half*)(smem + SQ_Y);
    float* C1s  = (float*)(smem + SQ_C1);
    float* ALs  = (float*)(smem + SQ_AL);
    float* BEs  = (float*)(smem + SQ_BE);
    float* FAw  = (float*)(smem + SQ_FW);
    float* FBw  = FAw + 160;
    float* PART = (float*)(smem + SQ_PART);

    int b = blk / 800;
    int rem = blk - b * 800;
    int sIdx = rem >> 2;                  // 0..199
    int s = 200 + sIdx;
    int q = rem & 3;                      // quarter: output rows q*5 .. q*5+4

    {
        uint4 z4 = make_uint4(0, 0, 0, 0);
        uint4* Yz = (uint4*)(smem + SQ_Y);
        for (int i = tid; i < 3060; i += 256) Yz[i] = z4;
    }

    int t0 = s * 256;
    int r0 = t0 % 400;
    int usplit = 400 - r0;
    if (usplit > 256) usplit = 256;
    int chA = t0 / 400 - 128;
    int chB = (usplit >= 256) ? chA : (chA + 1);

    if (tid < 128) {
        int o = tid;
        C1s[o] = g_C1[o];
        ALs[o] = g_AL[sIdx * 128 + o];
        BEs[o] = g_BE[sIdx * 128 + o];
    }
    for (int idx = tid; idx < 280; idx += 256) {
        int arr = idx / 140, pos = idx % 140;
        int rw = pos / 20, gw = pos % 20;
        int gh = q * 5 - 1 + rw;
        float v = 0.f;
        if (gh >= 0 && gh < 20)
            v = g_featC[b * 51200 + (arr ? chB : chA) * 400 + gh * 20 + gw];
        (arr ? FBw : FAw)[pos] = v;
    }
    __syncthreads();

    for (int idx = tid; idx < 280; idx += 256) {
        int chh = idx / 140, pos = idx % 140;
        int rw = pos / 20, gw = pos % 20;
        int gh = q * 5 - 1 + rw;
        if (gh >= 0 && gh < 20) {
            float fa = FAw[pos], fb = FBw[pos];
            int rowoff = (rw * 24 + gw + 1) * 136;
#pragma unroll 8
            for (int o2 = 0; o2 < 32; o2++) {
                int o = chh * 64 + o2 * 2;
                float y0 = silu_f(ALs[o] * fa + BEs[o] * fb + C1s[o]);
                float y1 = silu_f(ALs[o + 1] * fa + BEs[o + 1] * fb + C1s[o + 1]);
                *(__half2*)(Yh + rowoff + o) = __floats2half2_rn(y0, y1);
            }
        }
    }
    __syncthreads();

    int wm = wid & 3;
    int wn = wid >> 2;
    int nb = wn * 64;

    uint32_t Ybase = (uint32_t)__cvta_generic_to_shared(Yh);
    int laneN = lane & 7;
    int sel   = (lane >> 3) & 1;
    int pairN = lane >> 4;
    uint32_t laneTerm = Ybase + (uint32_t)((pairN * 8 + laneN) * 272 + sel * 16);

    float acc[2][8][4];
#pragma unroll
    for (int mt = 0; mt < 2; mt++)
#pragma unroll
        for (int nt = 0; nt < 8; nt++)
#pragma unroll
            for (int c = 0; c < 4; c++) acc[mt][nt][c] = 0.f;

    int mtile0 = wm * 2;
    const uint4* Aw0 = ((const uint4*)g_wAf) + ((mtile0 >> 2) * 1024 + (mtile0 & 3) * 32) + lane;
    const uint4* Aw1 = ((const uint4*)g_wAf) + (((mtile0 + 1) >> 2) * 1024 + ((mtile0 + 1) & 3) * 32) + lane;
    uint4 avc[2];
    avc[0] = __ldg(Aw0);
    avc[1] = __ldg(Aw1);

    uint32_t bv0[2][8], bv1[2][8];
    uint32_t rowa = laneTerm + (uint32_t)(nb * 272);
    ldsm_x4(bv0[0][0], bv1[0][0], bv0[0][1], bv1[0][1], rowa);
    ldsm_x4(bv0[0][2], bv1[0][2], bv0[0][3], bv1[0][3], rowa + 4352);
    ldsm_x4(bv0[0][4], bv1[0][4], bv0[0][5], bv1[0][5], rowa + 8704);
    ldsm_x4(bv0[0][6], bv1[0][6], bv0[0][7], bv1[0][7], rowa + 13056);

#pragma unroll 1
    for (int tap = 0; tap < 9; tap++) {
        int tap1 = (tap < 8) ? tap + 1 : 8;
        int dh1 = tap1 / 3, dw1 = tap1 - dh1 * 3;
        uint32_t rowan = laneTerm + (uint32_t)((nb + dh1 * 24 + dw1) * 272);
#pragma unroll
        for (int kk = 0; kk < 8; kk++) {
            int pp = kk & 1;
            int np = pp ^ 1;
            uint32_t na = (kk < 7) ? (rowa + (uint32_t)((kk + 1) * 32)) : rowan;
            ldsm_x4(bv0[np][0], bv1[np][0], bv0[np][1], bv1[np][1], na);
            ldsm_x4(bv0[np][2], bv1[np][2], bv0[np][3], bv1[np][3], na + 4352);
            ldsm_x4(bv0[np][4], bv1[np][4], bv0[np][5], bv1[np][5], na + 8704);
            ldsm_x4(bv0[np][6], bv1[np][6], bv0[np][7], bv1[np][7], na + 13056);
            int ntap = (kk == 7) ? tap + 1 : tap;
            int nkk = (kk + 1) & 7;
            uint4 avn[2];
            avn[0] = __ldg(Aw0 + ntap * 2048 + nkk * 128);
            avn[1] = __ldg(Aw1 + ntap * 2048 + nkk * 128);
#pragma unroll
            for (int mt = 0; mt < 2; mt++) {
#pragma unroll
                for (int nt = 0; nt < 8; nt++)
                    mma_f16(acc[mt][nt], avc[mt].x, avc[mt].y, avc[mt].z, avc[mt].w,
                            bv0[pp][nt], bv1[pp][nt]);
            }
            avc[0] = avn[0];
            avc[1] = avn[1];
        }
        rowa = rowan;
    }

    float a3 = g_bn3[0];
    float c3 = g_bn3[1];

    float pnt[8][2];
#pragma unroll
    for (int nt = 0; nt < 8; nt++) { pnt[nt][0] = 0.f; pnt[nt][1] = 0.f; }

#pragma unroll
    for (int mt = 0; mt < 2; mt++) {
#pragma unroll
        for (int rs = 0; rs < 2; rs++) {
            int m = wm * 32 + mt * 16 + rs * 8 + lg;
            float a2m = g_A2[m], c2m = g_C2[m], w3m = g_W3[m];
#pragma unroll
            for (int nt = 0; nt < 8; nt++) {
#pragma unroll
                for (int cc = 0; cc < 2; cc++) {
                    float zv = silu_f(a2m * acc[mt][nt][rs * 2 + cc] + c2m);
                    pnt[nt][cc] += w3m * zv;
                }
            }
        }
    }
#pragma unroll
    for (int nt = 0; nt < 8; nt++) {
#pragma unroll
        for (int cc = 0; cc < 2; cc++) {
            float v = pnt[nt][cc];
            v += __shfl_xor_sync(0xffffffffu, v, 4);
            v += __shfl_xor_sync(0xffffffffu, v, 8);
            v += __shfl_xor_sync(0xffffffffu, v, 16);
            if (lane < 4)
                PART[wm * 128 + nb + nt * 8 + 2 * lane + cc] = v;
        }
    }
    __syncthreads();

    if (tid < 128) {
        int n = tid;
        int hl = n / 24, wc = n % 24;
        if (hl < 5 && wc < 20) {
            float v = PART[n] + PART[128 + n] + PART[256 + n] + PART[384 + n];
            int h = q * 5 + hl;
            g_scores[(b * 400 + s) * 400 + h * 20 + wc] = silu_f(a3 * v + c3);
        }
    }
}

// ---------------- attention: 4 rows/CTA, coalesced featI, j/k 2-way split ----------------
__global__ __launch_bounds__(256)
void att_kernel(const float* __restrict__ x,
                const float* __restrict__ g2, const float* __restrict__ b2,
                const float* __restrict__ m2, const float* __restrict__ v2,
                float* __restrict__ out) {
    __shared__ float srow[4][400];
    __shared__ float attp[4][132];
    __shared__ float atts[4][132];
    __shared__ float yp[4][132];

    int blk = blockIdx.x;               // 200 = 2b * 50
    int b = blk / 100;
    int i0 = (blk % 100) * 4;
    int tid = threadIdx.x;              // 256
    int c = tid & 127;
    int g = tid >> 7;                   // 0,1

    for (int idx = tid; idx < 1600; idx += 256) {
        int r = idx / 400, j = idx - r * 400;
        srow[r][j] = g_scores[(b * 400 + i0 + r) * 400 + j];
    }
    __syncthreads();

    float acc[4] = {0.f, 0.f, 0.f, 0.f};
    {
        const float* fI = g_featI + b * 51200 + c;
        int j0 = g * 200;
#pragma unroll 4
        for (int j = j0; j < j0 + 200; j++) {
            float fv = fI[j * 128];
#pragma unroll
            for (int r = 0; r < 4; r++) acc[r] += srow[r][j] * fv;
        }
    }
    if (g) {
#pragma unroll
        for (int r = 0; r < 4; r++) attp[r][c] = acc[r];
    }
    __syncthreads();
    if (!g) {
#pragma unroll
        for (int r = 0; r < 4; r++) atts[r][c] = acc[r] + attp[r][c];
    }
    __syncthreads();

    float y[4] = {0.f, 0.f, 0.f, 0.f};
    {
        int k0 = g * 64;
#pragma unroll 8
        for (int k = k0; k < k0 + 64; k++) {
            float wv = g_w2T[k * 128 + c];
#pragma unroll
            for (int r = 0; r < 4; r++) y[r] += wv * atts[r][k];
        }
    }
    if (g) {
#pragma unroll
        for (int r = 0; r < 4; r++) yp[r][c] = y[r];
    }
    __syncthreads();
    if (!g) {
        float a  = g2[c] * rsqrtf(v2[c] + EPS);
        float cn = b2[c] - m2[c] * a;
#pragma unroll
        for (int r = 0; r < 4; r++) {
            int i = i0 + r;
            float yy = y[r] + yp[r][c];
            out[(b * 128 + c) * 400 + i] = silu_f(a * yy + cn) + x[(b * 128 + c) * 400 + i];
        }
    }
}

// ---------------- launcher ----------------
extern "C" void kernel_launch(void* const* d_in, const int* in_sizes, int n_in,
                              void* d_out, int out_size) {
    (void)in_sizes; (void)n_in; (void)out_size;
    const float* x   = (const float*)d_in[0];
    const float* w1  = (const float*)d_in[1];
    const float* g1  = (const float*)d_in[2];
    const float* b1  = (const float*)d_in[3];
    const float* m1  = (const float*)d_in[4];
    const float* v1  = (const float*)d_in[5];
    const float* w2  = (const float*)d_in[6];
    const float* g2  = (const float*)d_in[7];
    const float* b2  = (const float*)d_in[8];
    const float* m2  = (const float*)d_in[9];
    const float* v2  = (const float*)d_in[10];
    const float* wr1 = (const float*)d_in[11];
    const float* gr1 = (const float*)d_in[12];
    const float* br1 = (const float*)d_in[13];
    const float* mr1 = (const float*)d_in[14];
    const float* vr1 = (const float*)d_in[15];
    const float* wr2 = (const float*)d_in[16];
    const float* gr2 = (const float*)d_in[17];
    const float* br2 = (const float*)d_in[18];
    const float* mr2 = (const float*)d_in[19];
    const float* vr2 = (const float*)d_in[20];
    const float* wr3 = (const float*)d_in[21];
    const float* gr3 = (const float*)d_in[22];
    const float* br3 = (const float*)d_in[23];
    const float* mr3 = (const float*)d_in[24];
    const float* vr3 = (const float*)d_in[25];
    float* out = (float*)d_out;

    cudaFuncSetAttribute(big_kernel, cudaFuncAttributeMaxDynamicSharedMemorySize, SQ_TOT);

    // 4 launches; capture slot #4 lands on att_kernel (never profiled in this form).
    prep_all_kernel<<<264, 256>>>(wr2, w2, wr1, gr1, br1, mr1, vr1,
                                  gr2, br2, mr2, vr2, wr3, gr3, br3, mr3, vr3);
    feat_kernel<<<256, 256>>>(x, w1, g1, b1, m1, v1);
    big_kernel<<<1800, 256, SQ_TOT>>>(wr1, gr1, br1, mr1, vr1);
    att_kernel<<<200, 256>>>(x, g2, b2, m2, v2, out);
}